// round 1
// baseline (speedup 1.0000x reference)
#include <cuda_runtime.h>
#include <cuda_bf16.h>
#include <mma.h>

using namespace nvcuda;

#define NE 8
#define NTOK 8192
#define DDIM 1024
#define HDIM 2048
#define ODIM 1024
#define OUTC (ODIM + NE)   // 1032

#define BM 64
#define BN 64
#define BK 32

// ---- scratch (no allocations allowed: __device__ globals) ----
__device__ int   g_counts[NE];
__device__ int   g_offsets[NE];
__device__ int   g_cursor[NE];
__device__ int   g_perm[NTOK];
__device__ float g_hbuf[(size_t)NTOK * HDIM];   // 64 MB intermediate h

// ---------------- routing ----------------
__global__ void k_zero_counts() {
    if (threadIdx.x < NE) g_counts[threadIdx.x] = 0;
}

__global__ void k_count(const int* __restrict__ eidx) {
    int n = blockIdx.x * blockDim.x + threadIdx.x;
    if (n < NTOK) atomicAdd(&g_counts[eidx[n]], 1);
}

__global__ void k_offsets() {
    // single thread; E=8
    int acc = 0;
    for (int e = 0; e < NE; e++) {
        g_offsets[e] = acc;
        g_cursor[e]  = acc;
        acc += g_counts[e];
    }
}

__global__ void k_scatter(const int* __restrict__ eidx) {
    int n = blockIdx.x * blockDim.x + threadIdx.x;
    if (n < NTOK) {
        int e = eidx[n];
        int p = atomicAdd(&g_cursor[e], 1);
        g_perm[p] = n;
    }
}

// ---------------- GEMM1: h[perm-order] = gather(x) @ W1[e] + b1[e] ----------------
// grid: (HDIM/BN, NTOK/BM, NE), 128 threads (4 warps, 2x2 warp tile of 32x32)
__global__ void __launch_bounds__(128) k_gemm1(const float* __restrict__ x,
                                               const float* __restrict__ W1,
                                               const float* __restrict__ b1) {
    int e    = blockIdx.z;
    int Me   = g_counts[e];
    int row0 = blockIdx.y * BM;
    if (row0 >= Me) return;
    int base = g_offsets[e];
    int n0   = blockIdx.x * BN;

    const float* __restrict__ Wb  = W1 + (size_t)e * DDIM * HDIM;
    const float* __restrict__ b1e = b1 + (size_t)e * HDIM;

    __shared__ union {
        struct { float A[BM][BK + 4]; float B[BK][BN + 4]; } ab;
        float C[BM][BN + 8];  // stride 72 -> float4-aligned rows
    } sm;

    int tid  = threadIdx.x;
    int warp = tid >> 5;
    int wr   = warp >> 1;   // 0..1
    int wc   = warp & 1;    // 0..1

    wmma::fragment<wmma::accumulator, 16, 16, 8, float> acc[2][2];
    #pragma unroll
    for (int i = 0; i < 2; i++)
        #pragma unroll
        for (int j = 0; j < 2; j++)
            wmma::fill_fragment(acc[i][j], 0.0f);

    for (int k0 = 0; k0 < DDIM; k0 += BK) {
        // A tile: 64 rows x 32 cols, gathered via perm. 512 float4 loads.
        #pragma unroll
        for (int i = 0; i < 4; i++) {
            int lin = i * 128 + tid;
            int r   = lin >> 3;       // 0..63
            int c4  = lin & 7;        // 0..7
            float4 v = make_float4(0.f, 0.f, 0.f, 0.f);
            if (row0 + r < Me) {
                int t = g_perm[base + row0 + r];
                v = *reinterpret_cast<const float4*>(&x[(size_t)t * DDIM + k0 + c4 * 4]);
            }
            sm.ab.A[r][c4 * 4 + 0] = wmma::__float_to_tf32(v.x);
            sm.ab.A[r][c4 * 4 + 1] = wmma::__float_to_tf32(v.y);
            sm.ab.A[r][c4 * 4 + 2] = wmma::__float_to_tf32(v.z);
            sm.ab.A[r][c4 * 4 + 3] = wmma::__float_to_tf32(v.w);
        }
        // B tile: 32 rows x 64 cols (row-major [K,H]); 512 float4 loads.
        #pragma unroll
        for (int i = 0; i < 4; i++) {
            int lin = i * 128 + tid;
            int r   = lin >> 4;       // 0..31
            int c4  = lin & 15;       // 0..15
            float4 v = *reinterpret_cast<const float4*>(&Wb[(size_t)(k0 + r) * HDIM + n0 + c4 * 4]);
            sm.ab.B[r][c4 * 4 + 0] = wmma::__float_to_tf32(v.x);
            sm.ab.B[r][c4 * 4 + 1] = wmma::__float_to_tf32(v.y);
            sm.ab.B[r][c4 * 4 + 2] = wmma::__float_to_tf32(v.z);
            sm.ab.B[r][c4 * 4 + 3] = wmma::__float_to_tf32(v.w);
        }
        __syncthreads();

        #pragma unroll
        for (int kk = 0; kk < BK; kk += 8) {
            wmma::fragment<wmma::matrix_a, 16, 16, 8, wmma::precision::tf32, wmma::row_major> a0, a1;
            wmma::fragment<wmma::matrix_b, 16, 16, 8, wmma::precision::tf32, wmma::row_major> bf0, bf1;
            wmma::load_matrix_sync(a0,  &sm.ab.A[wr * 32 +  0][kk], BK + 4);
            wmma::load_matrix_sync(a1,  &sm.ab.A[wr * 32 + 16][kk], BK + 4);
            wmma::load_matrix_sync(bf0, &sm.ab.B[kk][wc * 32 +  0], BN + 4);
            wmma::load_matrix_sync(bf1, &sm.ab.B[kk][wc * 32 + 16], BN + 4);
            wmma::mma_sync(acc[0][0], a0, bf0, acc[0][0]);
            wmma::mma_sync(acc[0][1], a0, bf1, acc[0][1]);
            wmma::mma_sync(acc[1][0], a1, bf0, acc[1][0]);
            wmma::mma_sync(acc[1][1], a1, bf1, acc[1][1]);
        }
        __syncthreads();
    }

    // epilogue: stage C in smem, then bounds-checked coalesced store
    #pragma unroll
    for (int i = 0; i < 2; i++)
        #pragma unroll
        for (int j = 0; j < 2; j++)
            wmma::store_matrix_sync(&sm.C[wr * 32 + i * 16][wc * 32 + j * 16],
                                    acc[i][j], BN + 8, wmma::mem_row_major);
    __syncthreads();

    #pragma unroll
    for (int i = 0; i < 8; i++) {
        int lin = i * 128 + tid;
        int r   = lin >> 4;       // 0..63
        int c4  = lin & 15;       // 0..15
        if (row0 + r < Me) {
            float4 v = *reinterpret_cast<float4*>(&sm.C[r][c4 * 4]);
            const float4 bb = *reinterpret_cast<const float4*>(&b1e[n0 + c4 * 4]);
            v.x += bb.x; v.y += bb.y; v.z += bb.z; v.w += bb.w;
            *reinterpret_cast<float4*>(&g_hbuf[(size_t)(base + row0 + r) * HDIM + n0 + c4 * 4]) = v;
        }
    }
}

// ---------------- GEMM2: out[perm] = h @ W2[e] + b2[e] ----------------
// grid: (ODIM/BN, NTOK/BM, NE), 128 threads
__global__ void __launch_bounds__(128) k_gemm2(const float* __restrict__ W2,
                                               const float* __restrict__ b2,
                                               float* __restrict__ out) {
    int e    = blockIdx.z;
    int Me   = g_counts[e];
    int row0 = blockIdx.y * BM;
    if (row0 >= Me) return;
    int base = g_offsets[e];
    int n0   = blockIdx.x * BN;

    const float* __restrict__ Wb  = W2 + (size_t)e * HDIM * ODIM;
    const float* __restrict__ b2e = b2 + (size_t)e * ODIM;

    __shared__ union {
        struct { float A[BM][BK + 4]; float B[BK][BN + 4]; } ab;
        float C[BM][BN + 8];
    } sm;

    int tid  = threadIdx.x;
    int warp = tid >> 5;
    int wr   = warp >> 1;
    int wc   = warp & 1;

    wmma::fragment<wmma::accumulator, 16, 16, 8, float> acc[2][2];
    #pragma unroll
    for (int i = 0; i < 2; i++)
        #pragma unroll
        for (int j = 0; j < 2; j++)
            wmma::fill_fragment(acc[i][j], 0.0f);

    for (int k0 = 0; k0 < HDIM; k0 += BK) {
        #pragma unroll
        for (int i = 0; i < 4; i++) {
            int lin = i * 128 + tid;
            int r   = lin >> 3;
            int c4  = lin & 7;
            float4 v = make_float4(0.f, 0.f, 0.f, 0.f);
            if (row0 + r < Me) {
                v = *reinterpret_cast<const float4*>(
                        &g_hbuf[(size_t)(base + row0 + r) * HDIM + k0 + c4 * 4]);
            }
            sm.ab.A[r][c4 * 4 + 0] = wmma::__float_to_tf32(v.x);
            sm.ab.A[r][c4 * 4 + 1] = wmma::__float_to_tf32(v.y);
            sm.ab.A[r][c4 * 4 + 2] = wmma::__float_to_tf32(v.z);
            sm.ab.A[r][c4 * 4 + 3] = wmma::__float_to_tf32(v.w);
        }
        #pragma unroll
        for (int i = 0; i < 4; i++) {
            int lin = i * 128 + tid;
            int r   = lin >> 4;
            int c4  = lin & 15;
            float4 v = *reinterpret_cast<const float4*>(&Wb[(size_t)(k0 + r) * ODIM + n0 + c4 * 4]);
            sm.ab.B[r][c4 * 4 + 0] = wmma::__float_to_tf32(v.x);
            sm.ab.B[r][c4 * 4 + 1] = wmma::__float_to_tf32(v.y);
            sm.ab.B[r][c4 * 4 + 2] = wmma::__float_to_tf32(v.z);
            sm.ab.B[r][c4 * 4 + 3] = wmma::__float_to_tf32(v.w);
        }
        __syncthreads();

        #pragma unroll
        for (int kk = 0; kk < BK; kk += 8) {
            wmma::fragment<wmma::matrix_a, 16, 16, 8, wmma::precision::tf32, wmma::row_major> a0, a1;
            wmma::fragment<wmma::matrix_b, 16, 16, 8, wmma::precision::tf32, wmma::row_major> bf0, bf1;
            wmma::load_matrix_sync(a0,  &sm.ab.A[wr * 32 +  0][kk], BK + 4);
            wmma::load_matrix_sync(a1,  &sm.ab.A[wr * 32 + 16][kk], BK + 4);
            wmma::load_matrix_sync(bf0, &sm.ab.B[kk][wc * 32 +  0], BN + 4);
            wmma::load_matrix_sync(bf1, &sm.ab.B[kk][wc * 32 + 16], BN + 4);
            wmma::mma_sync(acc[0][0], a0, bf0, acc[0][0]);
            wmma::mma_sync(acc[0][1], a0, bf1, acc[0][1]);
            wmma::mma_sync(acc[1][0], a1, bf0, acc[1][0]);
            wmma::mma_sync(acc[1][1], a1, bf1, acc[1][1]);
        }
        __syncthreads();
    }

    #pragma unroll
    for (int i = 0; i < 2; i++)
        #pragma unroll
        for (int j = 0; j < 2; j++)
            wmma::store_matrix_sync(&sm.C[wr * 32 + i * 16][wc * 32 + j * 16],
                                    acc[i][j], BN + 8, wmma::mem_row_major);
    __syncthreads();

    // scatter rows back to original token positions
    #pragma unroll
    for (int i = 0; i < 8; i++) {
        int lin = i * 128 + tid;
        int r   = lin >> 4;
        int c4  = lin & 15;
        if (row0 + r < Me) {
            int t = g_perm[base + row0 + r];
            float4 v = *reinterpret_cast<float4*>(&sm.C[r][c4 * 4]);
            const float4 bb = *reinterpret_cast<const float4*>(&b2e[n0 + c4 * 4]);
            v.x += bb.x; v.y += bb.y; v.z += bb.z; v.w += bb.w;
            // row base t*1032 floats = 4128 B (16B multiple) -> float4 OK
            *reinterpret_cast<float4*>(&out[(size_t)t * OUTC + n0 + c4 * 4]) = v;
        }
    }
}

// ---------------- onehot tail columns ----------------
__global__ void k_onehot(const int* __restrict__ eidx, float* __restrict__ out) {
    int n = blockIdx.x * blockDim.x + threadIdx.x;
    if (n < NTOK) {
        int e = eidx[n];
        float4 lo = make_float4(e == 0 ? 1.f : 0.f, e == 1 ? 1.f : 0.f,
                                e == 2 ? 1.f : 0.f, e == 3 ? 1.f : 0.f);
        float4 hi = make_float4(e == 4 ? 1.f : 0.f, e == 5 ? 1.f : 0.f,
                                e == 6 ? 1.f : 0.f, e == 7 ? 1.f : 0.f);
        float* row = out + (size_t)n * OUTC + ODIM;
        *reinterpret_cast<float4*>(row)     = lo;   // base 16B-aligned
        *reinterpret_cast<float4*>(row + 4) = hi;
    }
}

// ---------------- launch ----------------
extern "C" void kernel_launch(void* const* d_in, const int* in_sizes, int n_in,
                              void* d_out, int out_size) {
    const float* x    = (const float*)d_in[0];
    const float* W1   = (const float*)d_in[1];
    const float* b1   = (const float*)d_in[2];
    const float* W2   = (const float*)d_in[3];
    const float* b2   = (const float*)d_in[4];
    const int*   eidx = (const int*)  d_in[5];
    float* out = (float*)d_out;

    k_zero_counts<<<1, 32>>>();
    k_count<<<NTOK / 256, 256>>>(eidx);
    k_offsets<<<1, 1>>>();
    k_scatter<<<NTOK / 256, 256>>>(eidx);

    dim3 g1(HDIM / BN, NTOK / BM, NE);   // (32, 128, 8); blocks past expert count early-exit
    k_gemm1<<<g1, 128>>>(x, W1, b1);

    dim3 g2(ODIM / BN, NTOK / BM, NE);   // (16, 128, 8)
    k_gemm2<<<g2, 128>>>(W2, b2, out);

    k_onehot<<<NTOK / 256, 256>>>(eidx, out);
}